// round 9
// baseline (speedup 1.0000x reference)
#include <cuda_runtime.h>
#include <cstdint>
#include <math.h>

#define TB 8192      // tokens = B*S
#define HD 1024
#define NE 8
#define FF 4096

// GEMM tiling: CTA 128x128, 4 warps (2x2), warptile 64x64
#define GT 128       // GEMM threads per CTA
#define BM 128
#define BN 128
#define KC 32
#define STAGES 3
#define ASTRIDE 36   // floats; frag-read bank = 4*lr + lc  (conflict-free)
#define BSTRIDE 136  // floats (128 data + 8 pad); frag-read bank = 8*lc + lr (conflict-free)

#define A_STG_F (BM * ASTRIDE)            // 4608 floats
#define B_STG_F (KC * BSTRIDE)            // 4352 floats
#define A_BYTES (STAGES * A_STG_F * 4)    // 55296
#define B_BYTES (STAGES * B_STG_F * 4)    // 52224
#define SMEM_SZ (A_BYTES + B_BYTES + 2048) // 109568 -> 2 CTA/SM

// ---- scratch (static device arrays; no allocation) ----
__device__ float g_x [(size_t)TB * HD];        // tf32-rounded x (written by router)
__device__ float g_h [(size_t)2 * TB * FF];    // gelu(x@W1) per slot (tf32-rounded)
__device__ int   g_cnt[NE];
__device__ int   g_tok[NE * TB];
__device__ int   g_slot[NE * TB];
__device__ float g_p0[TB];

// ---- helpers ----
__device__ __forceinline__ uint32_t smem_u32(const void* p) {
    uint32_t a;
    asm("{ .reg .u64 t; cvta.to.shared.u64 t, %1; cvt.u32.u64 %0, t; }" : "=r"(a) : "l"(p));
    return a;
}
__device__ __forceinline__ uint32_t f2tf32(float x) {
    uint32_t u;
    asm("cvt.rna.tf32.f32 %0, %1;" : "=r"(u) : "f"(x));
    return u;
}
__device__ __forceinline__ void cp16(uint32_t s, const void* g) {
    asm volatile("cp.async.cg.shared.global [%0], [%1], 16;" :: "r"(s), "l"(g));
}
#define CP_COMMIT() asm volatile("cp.async.commit_group;" ::: "memory")
#define CP_WAIT1()  asm volatile("cp.async.wait_group 1;" ::: "memory")

#define MMA_TF32(d, a, b) \
    asm volatile("mma.sync.aligned.m16n8k8.row.col.f32.tf32.tf32.f32 " \
        "{%0,%1,%2,%3}, {%4,%5,%6,%7}, {%8,%9}, {%0,%1,%2,%3};" \
        : "+f"((d)[0]), "+f"((d)[1]), "+f"((d)[2]), "+f"((d)[3]) \
        : "r"((a)[0]), "r"((a)[1]), "r"((a)[2]), "r"((a)[3]), \
          "r"((b)[0]), "r"((b)[1]))

__device__ __forceinline__ float fgelu(float v) {
    float z = 0.7978845608028654f * (v + 0.044715f * v * v * v);
    float e = __expf(2.0f * z);
    float t = 1.0f - 2.0f / (e + 1.0f);   // tanh(z)
    return 0.5f * v * (1.0f + t);
}

// ---------------------------------------------------------------------------
// Zero output + expert counters
// ---------------------------------------------------------------------------
__global__ void k_zero(float* __restrict__ out, int n4) {
    int i = blockIdx.x * blockDim.x + threadIdx.x;
    float4 z = make_float4(0.f, 0.f, 0.f, 0.f);
    for (int j = i; j < n4; j += gridDim.x * blockDim.x)
        ((float4*)out)[j] = z;
    if (i < NE) g_cnt[i] = 0;
}

// ---------------------------------------------------------------------------
// Router (also writes tf32-rounded x into g_x)
// ---------------------------------------------------------------------------
__global__ void k_router(const float* __restrict__ x,
                         const float* __restrict__ Wr,
                         const float* __restrict__ br) {
    int warp = (blockIdx.x * blockDim.x + threadIdx.x) >> 5;
    int lane = threadIdx.x & 31;
    if (warp >= TB) return;
    const float* xr = x + (size_t)warp * HD;
    uint32_t* gxr = (uint32_t*)g_x + (size_t)warp * HD;

    float acc[NE];
#pragma unroll
    for (int e = 0; e < NE; e++) acc[e] = 0.f;
    for (int h = lane; h < HD; h += 32) {
        float xv = xr[h];
        gxr[h] = f2tf32(xv);
        float4 w0 = *(const float4*)(Wr + h * NE);
        float4 w1 = *(const float4*)(Wr + h * NE + 4);
        acc[0] += xv * w0.x; acc[1] += xv * w0.y;
        acc[2] += xv * w0.z; acc[3] += xv * w0.w;
        acc[4] += xv * w1.x; acc[5] += xv * w1.y;
        acc[6] += xv * w1.z; acc[7] += xv * w1.w;
    }
#pragma unroll
    for (int e = 0; e < NE; e++)
#pragma unroll
        for (int off = 16; off > 0; off >>= 1)
            acc[e] += __shfl_xor_sync(0xffffffffu, acc[e], off);
    if (lane == 0) {
#pragma unroll
        for (int e = 0; e < NE; e++) acc[e] += br[e];
        int i1 = 0; float l1 = acc[0];
#pragma unroll
        for (int e = 1; e < NE; e++) if (acc[e] > l1) { l1 = acc[e]; i1 = e; }
        int i2 = -1; float l2 = -3.0e38f;
#pragma unroll
        for (int e = 0; e < NE; e++) if (e != i1 && acc[e] > l2) { l2 = acc[e]; i2 = e; }
        g_p0[warp] = 1.0f / (1.0f + expf(l2 - l1));
        int p = atomicAdd(&g_cnt[i1], 1);
        g_tok[i1 * TB + p]  = warp;
        g_slot[i1 * TB + p] = 2 * warp;
        p = atomicAdd(&g_cnt[i2], 1);
        g_tok[i2 * TB + p]  = warp;
        g_slot[i2 * TB + p] = 2 * warp + 1;
    }
}

// ---------------------------------------------------------------------------
// Grouped GEMM on mma.sync tf32. 128 threads, 4 warps (2x2), warptile 64x64.
// W loaded raw fp32; B fragments RNA-rounded to tf32 in-register before MMA.
// MODE 0: g_h[slot] = tf32(gelu(x[tok] @ W1[e] + b1[e]))        (K=HD, N over FF)
// MODE 1: out[tok] += p0 * (g_h[slot] @ W2[e] + b2[e])  (atomic) (K=FF, N over HD)
// ---------------------------------------------------------------------------
template <int MODE>
__global__ __launch_bounds__(GT, 2)
void k_gemm(const float* __restrict__ W, const float* __restrict__ bias,
            float* __restrict__ outp) {
    constexpr int KTOT = MODE ? FF : HD;
    constexpr int LDA  = MODE ? FF : HD;
    constexpr int WROW = MODE ? HD : FF;
    constexpr int OROW = MODE ? HD : FF;
    constexpr int NC   = KTOT / KC;

    const int e  = blockIdx.z;
    const int me = g_cnt[e];
    const int mt = blockIdx.y;
    if (mt * BM >= me) return;
    const int ntb = blockIdx.x * BN;

    extern __shared__ char smraw[];
    float* As = (float*)smraw;
    float* Bs = (float*)(smraw + A_BYTES);
    int*   stok  = (int*)(smraw + A_BYTES + B_BYTES);
    int*   sslot = stok + 128;
    float* sp0   = (float*)(sslot + 128);

    const int tid  = threadIdx.x;
    const int wid  = tid >> 5;
    const int lane = tid & 31;
    const int wm   = wid >> 1;       // 0..1
    const int wn   = wid & 1;        // 0..1
    const int lr   = lane >> 2;      // 0..7  (groupID)
    const int lc   = lane & 3;       // 0..3  (threadID_in_group)

    // token/slot lists (128 rows, 128 threads)
    {
        int i = mt * BM + tid;
        int tok = 0, slot = -1;
        if (i < me) { tok = g_tok[e * TB + i]; slot = g_slot[e * TB + i]; }
        stok[tid] = tok; sslot[tid] = slot;
        if (MODE == 1) sp0[tid] = g_p0[tok];
    }
    __syncthreads();

    // ---- cp.async mappings ----
    const float* Asrc = MODE ? (const float*)g_h : (const float*)g_x;
    const float* aptr[8];
#pragma unroll
    for (int m = 0; m < 8; m++) {
        int row = (tid >> 3) + 16 * m;
        int rid = MODE ? sslot[row] : stok[row];
        if (rid < 0) rid = 0;
        aptr[m] = Asrc + (size_t)rid * LDA + (tid & 7) * 4;
    }
    const uint32_t asmA = smem_u32(As) +
        (uint32_t)((tid >> 3) * ASTRIDE + (tid & 7) * 4) * 4;

    const int bkr = tid >> 2;
    const float* bglob = W + (size_t)e * HD * FF + (size_t)bkr * WROW + ntb + (tid & 3) * 4;
    const uint32_t bsmB = smem_u32(Bs) +
        (uint32_t)(bkr * BSTRIDE + (tid & 3) * 4) * 4;

#define LOAD_CHUNK(STG, C)                                                    \
    {                                                                         \
        uint32_t as_ = asmA + (STG) * (A_STG_F * 4);                          \
        _Pragma("unroll")                                                     \
        for (int m = 0; m < 8; m++)                                           \
            cp16(as_ + m * (16 * ASTRIDE * 4), aptr[m] + (C) * KC);           \
        const float* bg = bglob + (size_t)(C) * KC * WROW;                    \
        uint32_t bs_ = bsmB + (STG) * (B_STG_F * 4);                          \
        _Pragma("unroll")                                                     \
        for (int m = 0; m < 8; m++)                                           \
            cp16(bs_ + m * 64, bg + m * 16);                                  \
    }

    float acc[4][8][4];
#pragma unroll
    for (int i = 0; i < 4; i++)
#pragma unroll
        for (int j = 0; j < 8; j++)
#pragma unroll
            for (int r = 0; r < 4; r++) acc[i][j][r] = 0.f;

    LOAD_CHUNK(0, 0); CP_COMMIT();
    LOAD_CHUNK(1, 1); CP_COMMIT();

    const uint32_t* Au0 = (const uint32_t*)As + (wm * 64 + lr) * ASTRIDE + lc;
    const uint32_t* Bu0 = (const uint32_t*)Bs + lc * BSTRIDE + wn * 64 + lr;

    for (int c = 0; c < NC; c++) {
        // Wait for chunk c's data, then one barrier, then issue loads for c+2.
        CP_WAIT1();
        __syncthreads();
        const int pf = c + STAGES - 1;
        if (pf < NC) { LOAD_CHUNK(pf % STAGES, pf); }
        CP_COMMIT();

        const int st = c % STAGES;
        const uint32_t* Au = Au0 + st * A_STG_F;
        const uint32_t* Bu = Bu0 + st * B_STG_F;
#pragma unroll
        for (int k8 = 0; k8 < KC / 8; k8++) {
            const int ck = k8 * 8;
            uint32_t af[4][4], bf[8][2];
#pragma unroll
            for (int i = 0; i < 4; i++) {
                af[i][0] = Au[(16 * i) * ASTRIDE + ck];
                af[i][1] = Au[(16 * i + 8) * ASTRIDE + ck];
                af[i][2] = Au[(16 * i) * ASTRIDE + ck + 4];
                af[i][3] = Au[(16 * i + 8) * ASTRIDE + ck + 4];
            }
#pragma unroll
            for (int j = 0; j < 8; j++) {
                bf[j][0] = f2tf32(__uint_as_float(Bu[ck * BSTRIDE + 8 * j]));
                bf[j][1] = f2tf32(__uint_as_float(Bu[(ck + 4) * BSTRIDE + 8 * j]));
            }
#pragma unroll
            for (int i = 0; i < 4; i++)
#pragma unroll
                for (int j = 0; j < 8; j++)
                    MMA_TF32(acc[i][j], af[i], bf[j]);
        }
    }

    // ---- epilogue ----
    float bv[16];
#pragma unroll
    for (int j = 0; j < 8; j++) {
        float2 t = *(const float2*)(bias + e * OROW + ntb + wn * 64 + 8 * j + lc * 2);
        bv[2 * j] = t.x; bv[2 * j + 1] = t.y;
    }

#pragma unroll
    for (int i = 0; i < 4; i++) {
        const int mr0 = wm * 64 + 16 * i + lr;
        const int s0 = sslot[mr0];
        const int s1 = sslot[mr0 + 8];
#pragma unroll
        for (int j = 0; j < 8; j++) {
            const int n = ntb + wn * 64 + 8 * j + lc * 2;
            if (MODE == 0) {
                if (s0 >= 0) {
                    float2 v;
                    v.x = __uint_as_float(f2tf32(fgelu(acc[i][j][0] + bv[2 * j])));
                    v.y = __uint_as_float(f2tf32(fgelu(acc[i][j][1] + bv[2 * j + 1])));
                    *(float2*)(g_h + (size_t)s0 * OROW + n) = v;
                }
                if (s1 >= 0) {
                    float2 v;
                    v.x = __uint_as_float(f2tf32(fgelu(acc[i][j][2] + bv[2 * j])));
                    v.y = __uint_as_float(f2tf32(fgelu(acc[i][j][3] + bv[2 * j + 1])));
                    *(float2*)(g_h + (size_t)s1 * OROW + n) = v;
                }
            } else {
                if (s0 >= 0) {
                    float p = sp0[mr0];
                    float* op = outp + (size_t)stok[mr0] * HD + n;
                    atomicAdd(op,     p * (acc[i][j][0] + bv[2 * j]));
                    atomicAdd(op + 1, p * (acc[i][j][1] + bv[2 * j + 1]));
                }
                if (s1 >= 0) {
                    float p = sp0[mr0 + 8];
                    float* op = outp + (size_t)stok[mr0 + 8] * HD + n;
                    atomicAdd(op,     p * (acc[i][j][2] + bv[2 * j]));
                    atomicAdd(op + 1, p * (acc[i][j][3] + bv[2 * j + 1]));
                }
            }
        }
    }
}

// ---------------------------------------------------------------------------
extern "C" void kernel_launch(void* const* d_in, const int* in_sizes, int n_in,
                              void* d_out, int out_size) {
    const float* x  = (const float*)d_in[0];
    const float* Wr = (const float*)d_in[1];
    const float* br = (const float*)d_in[2];
    const float* W1 = (const float*)d_in[3];
    const float* b1 = (const float*)d_in[4];
    const float* W2 = (const float*)d_in[5];
    const float* b2 = (const float*)d_in[6];
    float* out = (float*)d_out;

    cudaFuncSetAttribute(k_gemm<0>, cudaFuncAttributeMaxDynamicSharedMemorySize, SMEM_SZ);
    cudaFuncSetAttribute(k_gemm<1>, cudaFuncAttributeMaxDynamicSharedMemorySize, SMEM_SZ);

    k_zero<<<2048, 256>>>(out, out_size / 4);
    k_router<<<TB / 8, 256>>>(x, Wr, br);
    dim3 g1(FF / BN, TB / BM, NE);   // (32, 64, 8)
    k_gemm<0><<<g1, GT, SMEM_SZ>>>(W1, b1, nullptr);
    dim3 g2(HD / BN, TB / BM, NE);   // (8, 64, 8)
    k_gemm<1><<<g2, GT, SMEM_SZ>>>(W2, b2, out);
}